// round 8
// baseline (speedup 1.0000x reference)
#include <cuda_runtime.h>
#include <math.h>

#define Tn 4
#define Bn 4
#define Cn 64
#define Ln 4096
#define NLAYERS 10
#define TL 64          // l-tile per block
#define LTHREADS 512

// ---------------- scratch (no allocations allowed) ----------------
__device__ float g_xA[Tn*Bn*Cn*Ln];     // 16 MB
__device__ float g_xB[Tn*Bn*Cn*Ln];     // 16 MB
__device__ float g_skip[Tn*Bn*Cn*Ln];   // 16 MB
__device__ float g_proj[NLAYERS*Bn*Cn];

// ---------------- packed f32x2 helpers ----------------
__device__ __forceinline__ unsigned long long pk2(float w){
    unsigned long long r;
    asm("mov.b64 %0, {%1, %1};" : "=l"(r) : "f"(w));
    return r;
}
__device__ __forceinline__ void f2fma(unsigned long long &d, unsigned long long a, unsigned long long b){
    asm("fma.rn.f32x2 %0, %1, %2, %0;" : "+l"(d) : "l"(a), "l"(b));
}
__device__ __forceinline__ float lo32(unsigned long long v){ return __uint_as_float((unsigned)v); }
__device__ __forceinline__ float hi32(unsigned long long v){ return __uint_as_float((unsigned)(v>>32)); }

// ---------------- JAX threefry2x32 (key = (0,42)) ----------------
__device__ __forceinline__ unsigned rotl32(unsigned x, int r){ return (x<<r)|(x>>(32-r)); }

__device__ __forceinline__ void threefry_0_42(unsigned x0, unsigned x1, unsigned &o0, unsigned &o1){
    const unsigned ks0 = 0u, ks1 = 42u, ks2 = 0u ^ 42u ^ 0x1BD11BDAu;
    x0 += ks0; x1 += ks1;
#define TF_RND(r) { x0 += x1; x1 = rotl32(x1,(r)); x1 ^= x0; }
    TF_RND(13) TF_RND(15) TF_RND(26) TF_RND(6)
    x0 += ks1; x1 += ks2 + 1u;
    TF_RND(17) TF_RND(29) TF_RND(16) TF_RND(24)
    x0 += ks2; x1 += ks0 + 2u;
    TF_RND(13) TF_RND(15) TF_RND(26) TF_RND(6)
    x0 += ks0; x1 += ks1 + 3u;
    TF_RND(17) TF_RND(29) TF_RND(16) TF_RND(24)
    x0 += ks1; x1 += ks2 + 4u;
    TF_RND(13) TF_RND(15) TF_RND(26) TF_RND(6)
    x0 += ks2; x1 += ks0 + 5u;
#undef TF_RND
    o0 = x0; o1 = x1;
}
__device__ __forceinline__ float bits2unit(unsigned b){
    return __uint_as_float((b >> 9) | 0x3f800000u) - 1.0f;
}

// ---------------- encoder: poisson + input conv(1x1) + LIF ----------------
__global__ void __launch_bounds__(256) enc_kernel(const float* __restrict__ audio,
                                                  const float* __restrict__ w_in,
                                                  const float* __restrict__ b_in){
    int g = blockIdx.x * 256 + threadIdx.x;      // 0..16383  (b,l)
    int b = g >> 12, l = g & (Ln - 1);
    float a = audio[g];

    unsigned n0 = (unsigned)(b * Ln + l);        // t=0; partner t=2
    unsigned o0, o1, o2, o3;
    threefry_0_42(n0,           n0 + 32768u, o0, o2);
    threefry_0_42(n0 + 16384u,  n0 + 49152u, o1, o3);   // t=1 ; partner t=3

    float sp[4];
    sp[0] = (bits2unit(o0) < a) ? 1.f : 0.f;
    sp[1] = (bits2unit(o1) < a) ? 1.f : 0.f;
    sp[2] = (bits2unit(o2) < a) ? 1.f : 0.f;
    sp[3] = (bits2unit(o3) < a) ? 1.f : 0.f;

    for (int c = 0; c < Cn; c++){
        float w = w_in[c], bi = b_in[c];
        float v = 0.f;
#pragma unroll
        for (int t = 0; t < Tn; t++){
            float x = w * sp[t] + bi;
            v = v + __fdiv_rn(x - v, 1.2f);
            float s = (v >= 0.5f) ? 1.f : 0.f;
            v *= (1.f - s);
            int idx = ((t*Bn + b)*Cn + c)*Ln + l;
            g_xA[idx] = s;
        }
    }
}

// ---------------- ALL layers' diffusion-step embedding + projection ----------------
__global__ void __launch_bounds__(256) proj_all_kernel(const int* __restrict__ dstep,
                                                       const float* __restrict__ w1a,
                                                       const float* __restrict__ b1a,
                                                       const float* __restrict__ w2a,
                                                       const float* __restrict__ b2a,
                                                       const float* __restrict__ dpwa,
                                                       const float* __restrict__ dpba){
    int i = blockIdx.x;   // layer
    const float* w1 = w1a + i*Cn;
    const float* b1 = b1a + i*Cn;
    const float* w2 = w2a + i*Cn*Cn;
    const float* b2 = b2a + i*Cn;
    const float* dpw = dpwa + i*Cn*Cn;
    const float* dpb = dpba + i*Cn;

    __shared__ float h[Bn][Cn];
    __shared__ float e[Bn][Cn];
    int tid = threadIdx.x;
    int b = tid >> 6, c = tid & 63;

    float d = (float)dstep[b];
    float z = d * w1[c] + b1[c];
    float sg = 1.f / (1.f + expf(-z));
    h[b][c] = z * sg;                     // silu
    __syncthreads();

    float acc = b2[c];
    for (int j = 0; j < Cn; j++) acc += h[b][j] * w2[c*Cn + j];
    e[b][c] = acc;
    __syncthreads();

    float p = dpb[c];
    for (int j = 0; j < Cn; j++) p += e[b][j] * dpw[c*Cn + j];
    g_proj[i*Bn*Cn + b*Cn + c] = p;
}

// ---------------- fused layer: 2-timestep dilated conv + LIF + gate + skip/res 1x1 ----
// 512 threads; warp = 4 cg x 8 lg (wavefront-minimal):
//   lg = tid&7 (4 l each), cg = (tid>>3)&31, hl = tid>>8 -> l offset 0 or 32
__global__ void __launch_bounds__(LTHREADS, 1) layer_kernel(int flip, int layer,
                                                       const float* __restrict__ wconv,
                                                       const float* __restrict__ bconv,
                                                       const float* __restrict__ wskip,
                                                       const float* __restrict__ bskip,
                                                       const float* __restrict__ wres,
                                                       const float* __restrict__ bres,
                                                       int dil){
    const float* x_in  = flip ? g_xB : g_xA;
    float*       x_out = flip ? g_xA : g_xB;

    extern __shared__ float sm[];
    float* wc4  = sm;            // [ci][32 cg][k0:4co, k1:4co, k2:4co]  24576
    float* wskr = wc4  + 24576;  // [ci][32 cg][ws,ws32,wr,wr32]          8192
    float* cb   = wskr + 8192;   // 128
    float* pr   = cb   + 128;    // 64
    float* sbv  = pr   + 64;     // 64
    float* rbv  = sbv  + 64;     // 64
    float* ck   = rbv  + 64;     // [3][128] proj-fold constants          384
    float* tile = ck   + 384;    // 2 timesteps x 3 shifts x [64 ci][64 l] = 24576
                                 // gated overlay (stride 64) reuses s=0 region per timestep
                                 // total = 58048 floats = 232192 B

    const int tid  = threadIdx.x;
    const int b    = blockIdx.y;
    const int l0   = blockIdx.x * TL;
    const int cg   = (tid >> 3) & 31;
    const int jA   = ((tid & 7) << 2) + ((tid >> 8) << 5);   // lg*4 + hl*32

    // ---- coalesced weight load + scatter repack ----
    for (int i = tid; i < 24576; i += LTHREADS){
        int co = i / 192, r = i % 192, ci = r / 3, k = r % 3;
        int g = co >> 5, cgi = co & 31;
        wc4[((ci*32 + cgi)*3 + k)*4 + g] = wconv[i];
    }
    for (int i = tid; i < 4096; i += LTHREADS){
        int co = i >> 6, ci = i & 63;
        int g = co >> 5, cgi = co & 31;
        wskr[(ci*32 + cgi)*4 + g    ] = wskip[i];
        wskr[(ci*32 + cgi)*4 + g + 2] = wres[i];
    }
    if (tid < 128) cb[tid] = bconv[tid];
    if (tid < 64){
        pr[tid]  = g_proj[layer*Bn*Cn + b*Cn + tid];
        sbv[tid] = bskip[tid];
        rbv[tid] = bres[tid];
    }
    __syncthreads();

    // ---- proj-fold constants: ck[k][cout] = sum_ci wconv[cout,ci,k] * proj[ci] ----
    if (tid < 384){
        int k = tid >> 7;          // 0..2
        int cout = tid & 127;
        int cgi = cout & 31, g = cout >> 5;
        float acc = 0.f;
        for (int ci = 0; ci < Cn; ci++)
            acc += wc4[((ci*32 + cgi)*3 + k)*4 + g] * pr[ci];
        ck[(k << 7) + cout] = acc;
    }
    __syncthreads();

    const float SG1 = 1.f / (1.f + expf(-1.f));
    const float TH1 = tanhf(1.f);

    // folded bias: cb + ck0 + ck1 + ck2
    const unsigned long long cb0 = pk2(cb[cg]    + ck[cg]     + ck[128+cg]     + ck[256+cg]);
    const unsigned long long cb1 = pk2(cb[cg+32] + ck[cg+32]  + ck[128+cg+32]  + ck[256+cg+32]);
    const unsigned long long cb2 = pk2(cb[cg+64] + ck[cg+64]  + ck[128+cg+64]  + ck[256+cg+64]);
    const unsigned long long cb3 = pk2(cb[cg+96] + ck[cg+96]  + ck[128+cg+96]  + ck[256+cg+96]);
    const float sb0 = sbv[cg], sb1 = sbv[cg+32];
    const float rb0 = rbv[cg], rb1 = rbv[cg+32];

    const bool edge = (l0 < dil) || (l0 + TL + dil > Ln);
    float c00=0.f,c01=0.f,c02=0.f,c03=0.f,c20=0.f,c21=0.f,c22=0.f,c23=0.f;
    if (edge){
        c00 = ck[cg];       c01 = ck[cg+32];       c02 = ck[cg+64];       c03 = ck[cg+96];
        c20 = ck[256+cg];   c21 = ck[256+cg+32];   c22 = ck[256+cg+64];   c23 = ck[256+cg+96];
    }

    // LIF membrane: 4 couts x 4 l (persist across tt iterations)
    float vg0[4], vg1[4], vf0[4], vf1[4];
#pragma unroll
    for (int k = 0; k < 4; k++){ vg0[k]=0.f; vg1[k]=0.f; vf0[k]=0.f; vf1[k]=0.f; }

    for (int tt = 0; tt < 2; tt++){
        const int t0 = tt * 2;

        // ---- stage raw x tiles, zero-padded: cp.async path for dil>=4 ----
        if (dil >= 4){
#pragma unroll
            for (int k = 0; k < 2; k++){
                const float* xk = x_in + ((size_t)((t0+k)*Bn + b)) * Cn * Ln;
#pragma unroll
                for (int s = 0; s < 3; s++){
                    int off = l0 + (s - 1) * dil;
#pragma unroll
                    for (int w = 0; w < 2; w++){
                        int q  = tid + w*LTHREADS;   // 0..1023
                        int ci = q >> 4;
                        int jc = (q & 15) << 2;
                        int gl = off + jc;
                        unsigned ss = ((unsigned)gl <= 4092u) ? 16u : 0u;
                        const float* src = ss ? (xk + ci*Ln + gl) : xk;
                        unsigned daddr = (unsigned)__cvta_generic_to_shared(
                                             tile + k*12288 + s*4096 + (ci<<6) + jc);
                        asm volatile("cp.async.ca.shared.global [%0], [%1], 16, %2;"
                                     :: "r"(daddr), "l"(src), "r"(ss) : "memory");
                    }
                }
            }
            asm volatile("cp.async.commit_group;" ::: "memory");
            asm volatile("cp.async.wait_group 0;" ::: "memory");
        } else {
            // scalar path (dil = 1 or 2): raw x, zero-padded
#pragma unroll
            for (int k = 0; k < 2; k++){
                const float* xk = x_in + ((size_t)((t0+k)*Bn + b)) * Cn * Ln;
                float* tk = tile + k*12288;
#pragma unroll 4
                for (int i = tid; i < 3*Cn*TL; i += LTHREADS){
                    int s  = i >> 12;
                    int r  = i & 4095;
                    int ci = r >> 6; int j = r & 63;
                    int gl = l0 + j + (s - 1) * dil;
                    float val = 0.f;
                    if ((unsigned)gl < (unsigned)Ln) val = xk[ci*Ln + gl];
                    tk[i] = val;
                }
            }
        }
        __syncthreads();   // S1: tiles ready

        // ---- dilated conv, 4 couts x 4 l x 2 timesteps per thread ----
        unsigned long long aG0[2][2], aG1[2][2], aF0[2][2], aF1[2][2];
#pragma unroll
        for (int k = 0; k < 2; k++)
#pragma unroll
        for (int q = 0; q < 2; q++){ aG0[k][q]=cb0; aG1[k][q]=cb1; aF0[k][q]=cb2; aF1[k][q]=cb3; }

#pragma unroll 2
        for (int ci = 0; ci < Cn; ci++){
            const float* wrow = wc4 + (ci*32 + cg)*12;
            float4 k0 = *(const float4*)(wrow);
            float4 k1 = *(const float4*)(wrow + 4);
            float4 k2 = *(const float4*)(wrow + 8);
            unsigned long long w00=pk2(k0.x), w01=pk2(k1.x), w02=pk2(k2.x);
            unsigned long long w10=pk2(k0.y), w11=pk2(k1.y), w12=pk2(k2.y);
            unsigned long long w20=pk2(k0.z), w21=pk2(k1.z), w22=pk2(k2.z);
            unsigned long long w30=pk2(k0.w), w31=pk2(k1.w), w32=pk2(k2.w);
#pragma unroll
            for (int k = 0; k < 2; k++){
                const float* trow = tile + k*12288 + (ci << 6);
                ulonglong2 aA = *(const ulonglong2*)(trow + jA);
                ulonglong2 zA = *(const ulonglong2*)(trow + 4096 + jA);
                ulonglong2 pA = *(const ulonglong2*)(trow + 8192 + jA);
                f2fma(aG0[k][0], w00, aA.x); f2fma(aG0[k][1], w00, aA.y);
                f2fma(aG0[k][0], w01, zA.x); f2fma(aG0[k][1], w01, zA.y);
                f2fma(aG0[k][0], w02, pA.x); f2fma(aG0[k][1], w02, pA.y);

                f2fma(aG1[k][0], w10, aA.x); f2fma(aG1[k][1], w10, aA.y);
                f2fma(aG1[k][0], w11, zA.x); f2fma(aG1[k][1], w11, zA.y);
                f2fma(aG1[k][0], w12, pA.x); f2fma(aG1[k][1], w12, pA.y);

                f2fma(aF0[k][0], w20, aA.x); f2fma(aF0[k][1], w20, aA.y);
                f2fma(aF0[k][0], w21, zA.x); f2fma(aF0[k][1], w21, zA.y);
                f2fma(aF0[k][0], w22, pA.x); f2fma(aF0[k][1], w22, pA.y);

                f2fma(aF1[k][0], w30, aA.x); f2fma(aF1[k][1], w30, aA.y);
                f2fma(aF1[k][0], w31, zA.x); f2fma(aF1[k][1], w31, zA.y);
                f2fma(aF1[k][0], w32, pA.x); f2fma(aF1[k][1], w32, pA.y);
            }
        }

        // ---- LIF (hard reset) + gating, both timesteps in order ----
        float gb0[2][4], gb1[2][4];
#pragma unroll
        for (int k = 0; k < 2; k++){
#pragma unroll
            for (int q = 0; q < 2; q++){
#pragma unroll
                for (int h = 0; h < 2; h++){
                    int idx = 2*q + h;
                    float xg0 = h ? hi32(aG0[k][q]) : lo32(aG0[k][q]);
                    float xg1 = h ? hi32(aG1[k][q]) : lo32(aG1[k][q]);
                    float xf0 = h ? hi32(aF0[k][q]) : lo32(aF0[k][q]);
                    float xf1 = h ? hi32(aF1[k][q]) : lo32(aF1[k][q]);

                    if (edge){
                        int gl = l0 + jA + idx;
                        float f0 = (gl < dil) ? 1.f : 0.f;
                        float f2 = (gl >= Ln - dil) ? 1.f : 0.f;
                        xg0 -= f0*c00 + f2*c20;
                        xg1 -= f0*c01 + f2*c21;
                        xf0 -= f0*c02 + f2*c22;
                        xf1 -= f0*c03 + f2*c23;
                    }

                    vg0[idx] = vg0[idx] + __fdiv_rn(xg0 - vg0[idx], 1.2f);
                    float s_g0 = (vg0[idx] >= 0.5f) ? 1.f : 0.f;
                    vg0[idx] *= (1.f - s_g0);
                    vg1[idx] = vg1[idx] + __fdiv_rn(xg1 - vg1[idx], 1.2f);
                    float s_g1 = (vg1[idx] >= 0.5f) ? 1.f : 0.f;
                    vg1[idx] *= (1.f - s_g1);
                    vf0[idx] = vf0[idx] + __fdiv_rn(xf0 - vf0[idx], 1.2f);
                    float s_f0 = (vf0[idx] >= 0.5f) ? 1.f : 0.f;
                    vf0[idx] *= (1.f - s_f0);
                    vf1[idx] = vf1[idx] + __fdiv_rn(xf1 - vf1[idx], 1.2f);
                    float s_f1 = (vf1[idx] >= 0.5f) ? 1.f : 0.f;
                    vf1[idx] *= (1.f - s_f1);

                    gb0[k][idx] = ((s_g0 > 0.f) ? SG1 : 0.5f) * ((s_f0 > 0.f) ? TH1 : 0.f);
                    gb1[k][idx] = ((s_g1 > 0.f) ? SG1 : 0.5f) * ((s_f1 > 0.f) ? TH1 : 0.f);
                }
            }
        }
        __syncthreads();   // S2: conv reads of tile done -> safe to overlay gated into s=0 region

#pragma unroll
        for (int k = 0; k < 2; k++){
            float* g0 = tile + k*12288 + (cg << 6);
            float* g1 = tile + k*12288 + ((cg+32) << 6);
            *(float4*)(g0 + jA) = make_float4(gb0[k][0], gb0[k][1], gb0[k][2], gb0[k][3]);
            *(float4*)(g1 + jA) = make_float4(gb1[k][0], gb1[k][1], gb1[k][2], gb1[k][3]);
        }
        __syncthreads();   // S3: gated visible

        // ---- skip / res 1x1 convs for both timesteps (gated in s=0 overlay) ----
        unsigned long long sk0[2][2], sk1[2][2], rs0[2][2], rs1[2][2];
#pragma unroll
        for (int k = 0; k < 2; k++)
#pragma unroll
        for (int q = 0; q < 2; q++){ sk0[k][q]=0ull; sk1[k][q]=0ull; rs0[k][q]=0ull; rs1[k][q]=0ull; }

#pragma unroll 4
        for (int ci = 0; ci < Cn; ci++){
            float4 wv = *(const float4*)(wskr + (ci*32 + cg)*4);
            unsigned long long ws0 = pk2(wv.x), ws1 = pk2(wv.y);
            unsigned long long wr0 = pk2(wv.z), wr1 = pk2(wv.w);
#pragma unroll
            for (int k = 0; k < 2; k++){
                const float* grow = tile + k*12288 + (ci << 6);
                ulonglong2 gA = *(const ulonglong2*)(grow + jA);
                f2fma(sk0[k][0], ws0, gA.x); f2fma(sk0[k][1], ws0, gA.y);
                f2fma(sk1[k][0], ws1, gA.x); f2fma(sk1[k][1], ws1, gA.y);
                f2fma(rs0[k][0], wr0, gA.x); f2fma(rs0[k][1], wr0, gA.y);
                f2fma(rs1[k][0], wr1, gA.x); f2fma(rs1[k][1], wr1, gA.y);
            }
        }

        // ---- global update: skip RMW; x_out = x(center tap smem) + res ----
#pragma unroll
        for (int k = 0; k < 2; k++){
#pragma unroll
            for (int ch = 0; ch < 2; ch++){
                int co = cg + ch*32;
                unsigned long long* skp = ch ? sk1[k] : sk0[k];
                unsigned long long* rsp = ch ? rs1[k] : rs0[k];
                float sbp = ch ? sb1 : sb0;
                float rbp = ch ? rb1 : rb0;
                size_t gbase = ((size_t)((t0+k)*Bn + b)*Cn + co)*Ln + l0;
                float4 sv0 = make_float4(lo32(skp[0])+sbp, hi32(skp[0])+sbp,
                                         lo32(skp[1])+sbp, hi32(skp[1])+sbp);
                float4* skA = (float4*)(g_skip + gbase + jA);
                if (layer != 0){
                    float4 o0 = *skA;
                    sv0.x += o0.x; sv0.y += o0.y; sv0.z += o0.z; sv0.w += o0.w;
                }
                *skA = sv0;

                if (layer != NLAYERS-1){
                    // raw x center tap lives in smem (s=1 region untouched by overlay)
                    float4 a0 = *(const float4*)(tile + k*12288 + 4096 + (co << 6) + jA);
                    a0.x += lo32(rsp[0])+rbp; a0.y += hi32(rsp[0])+rbp;
                    a0.z += lo32(rsp[1])+rbp; a0.w += hi32(rsp[1])+rbp;
                    *(float4*)(x_out + gbase + jA) = a0;
                }
            }
        }
        __syncthreads();   // S4: overlay reads done -> next staging may write tile
    }
}

// ---------------- final: relu(skip) -> 1x1 conv -> LIF -> sum over T ----------------
__global__ void __launch_bounds__(256) out_kernel(const float* __restrict__ wout,
                                                  const float* __restrict__ bout,
                                                  float* __restrict__ out){
    int g = blockIdx.x * 256 + threadIdx.x;     // (b,l)
    int b = g >> 12, l = g & (Ln - 1);
    float bo = bout[0];
    float v = 0.f, ssum = 0.f;
#pragma unroll
    for (int t = 0; t < Tn; t++){
        float acc = bo;
        const float* sk = g_skip + ((size_t)(t*Bn + b))*Cn*Ln + l;
        for (int c = 0; c < Cn; c++){
            float s = sk[(size_t)c*Ln];
            s = (s > 0.f) ? s : 0.f;
            acc += wout[c] * s;
        }
        v = v + __fdiv_rn(acc - v, 1.2f);
        float sp = (v >= 0.5f) ? 1.f : 0.f;
        v *= (1.f - sp);
        ssum += sp;
    }
    out[g] = ssum;
}

// ---------------- launch ----------------
extern "C" void kernel_launch(void* const* d_in, const int* in_sizes, int n_in,
                              void* d_out, int out_size){
    const float* audio   = (const float*)d_in[0];
    const int*   dstep   = (const int*)  d_in[1];
    const float* W_in    = (const float*)d_in[2];
    const float* b_in    = (const float*)d_in[3];
    const float* demb_w1 = (const float*)d_in[4];
    const float* demb_b1 = (const float*)d_in[5];
    const float* demb_w2 = (const float*)d_in[6];
    const float* demb_b2 = (const float*)d_in[7];
    const float* dproj_w = (const float*)d_in[8];
    const float* dproj_b = (const float*)d_in[9];
    const float* conv_w  = (const float*)d_in[10];
    const float* conv_b  = (const float*)d_in[11];
    const float* skip_w  = (const float*)d_in[12];
    const float* skip_b  = (const float*)d_in[13];
    const float* res_w   = (const float*)d_in[14];
    const float* res_b   = (const float*)d_in[15];
    const float* W_out   = (const float*)d_in[16];
    const float* b_out   = (const float*)d_in[17];

    const int SMEM_BYTES = 58048 * 4;   // 232192
    cudaFuncSetAttribute((const void*)layer_kernel,
                         cudaFuncAttributeMaxDynamicSharedMemorySize, SMEM_BYTES);

    enc_kernel<<<(Bn*Ln)/256, 256>>>(audio, W_in, b_in);

    proj_all_kernel<<<NLAYERS, 256>>>(dstep, demb_w1, demb_b1, demb_w2, demb_b2,
                                      dproj_w, dproj_b);

    int flip = 0;
    for (int i = 0; i < NLAYERS; i++){
        layer_kernel<<<dim3(Ln/TL, Bn), LTHREADS, SMEM_BYTES>>>(flip, i,
                                conv_w + i*2*Cn*Cn*3, conv_b + i*2*Cn,
                                skip_w + i*Cn*Cn,     skip_b + i*Cn,
                                res_w  + i*Cn*Cn,     res_b  + i*Cn,
                                1 << i);
        flip ^= 1;
    }

    out_kernel<<<(Bn*Ln)/256, 256>>>(W_out, b_out, (float*)d_out);
}

// round 9
// speedup vs baseline: 1.6551x; 1.6551x over previous
#include <cuda_runtime.h>
#include <math.h>

#define Tn 4
#define Bn 4
#define Cn 64
#define Ln 4096
#define NLAYERS 10
#define TL 64          // l-tile per block
#define LTHREADS 512
#define RCP_TAU (1.0f/1.2f)   // compile-time RN constant

// ---------------- scratch (no allocations allowed) ----------------
__device__ float g_xA[Tn*Bn*Cn*Ln];     // 16 MB
__device__ float g_xB[Tn*Bn*Cn*Ln];     // 16 MB
__device__ float g_skip[Tn*Bn*Cn*Ln];   // 16 MB
__device__ float g_proj[NLAYERS*Bn*Cn];

// ---------------- packed f32x2 helpers ----------------
__device__ __forceinline__ unsigned long long pk2(float w){
    unsigned long long r;
    asm("mov.b64 %0, {%1, %1};" : "=l"(r) : "f"(w));
    return r;
}
__device__ __forceinline__ void f2fma(unsigned long long &d, unsigned long long a, unsigned long long b){
    asm("fma.rn.f32x2 %0, %1, %2, %0;" : "+l"(d) : "l"(a), "l"(b));
}
__device__ __forceinline__ float lo32(unsigned long long v){ return __uint_as_float((unsigned)v); }
__device__ __forceinline__ float hi32(unsigned long long v){ return __uint_as_float((unsigned)(v>>32)); }

// LIF update: v' = v + (x - v) * (1/tau)  [1-ulp-equivalent to /1.2, empirically safe]
__device__ __forceinline__ void lif_step(float &v, float x, float &spike){
    v = fmaf(x - v, RCP_TAU, v);
    spike = (v >= 0.5f) ? 1.f : 0.f;
    v *= (1.f - spike);
}

// ---------------- JAX threefry2x32 (key = (0,42)) ----------------
__device__ __forceinline__ unsigned rotl32(unsigned x, int r){ return (x<<r)|(x>>(32-r)); }

__device__ __forceinline__ void threefry_0_42(unsigned x0, unsigned x1, unsigned &o0, unsigned &o1){
    const unsigned ks0 = 0u, ks1 = 42u, ks2 = 0u ^ 42u ^ 0x1BD11BDAu;
    x0 += ks0; x1 += ks1;
#define TF_RND(r) { x0 += x1; x1 = rotl32(x1,(r)); x1 ^= x0; }
    TF_RND(13) TF_RND(15) TF_RND(26) TF_RND(6)
    x0 += ks1; x1 += ks2 + 1u;
    TF_RND(17) TF_RND(29) TF_RND(16) TF_RND(24)
    x0 += ks2; x1 += ks0 + 2u;
    TF_RND(13) TF_RND(15) TF_RND(26) TF_RND(6)
    x0 += ks0; x1 += ks1 + 3u;
    TF_RND(17) TF_RND(29) TF_RND(16) TF_RND(24)
    x0 += ks1; x1 += ks2 + 4u;
    TF_RND(13) TF_RND(15) TF_RND(26) TF_RND(6)
    x0 += ks2; x1 += ks0 + 5u;
#undef TF_RND
    o0 = x0; o1 = x1;
}
__device__ __forceinline__ float bits2unit(unsigned b){
    return __uint_as_float((b >> 9) | 0x3f800000u) - 1.0f;
}

// ---------------- encoder: poisson + input conv(1x1) + LIF ----------------
__global__ void __launch_bounds__(256) enc_kernel(const float* __restrict__ audio,
                                                  const float* __restrict__ w_in,
                                                  const float* __restrict__ b_in){
    int g = blockIdx.x * 256 + threadIdx.x;      // 0..16383  (b,l)
    int b = g >> 12, l = g & (Ln - 1);
    float a = audio[g];

    unsigned n0 = (unsigned)(b * Ln + l);        // t=0; partner t=2
    unsigned o0, o1, o2, o3;
    threefry_0_42(n0,           n0 + 32768u, o0, o2);
    threefry_0_42(n0 + 16384u,  n0 + 49152u, o1, o3);   // t=1 ; partner t=3

    float sp[4];
    sp[0] = (bits2unit(o0) < a) ? 1.f : 0.f;
    sp[1] = (bits2unit(o1) < a) ? 1.f : 0.f;
    sp[2] = (bits2unit(o2) < a) ? 1.f : 0.f;
    sp[3] = (bits2unit(o3) < a) ? 1.f : 0.f;

    for (int c = 0; c < Cn; c++){
        float w = w_in[c], bi = b_in[c];
        float v = 0.f;
#pragma unroll
        for (int t = 0; t < Tn; t++){
            float x = w * sp[t] + bi;
            float s; lif_step(v, x, s);
            int idx = ((t*Bn + b)*Cn + c)*Ln + l;
            g_xA[idx] = s;
        }
    }
}

// ---------------- ALL layers' diffusion-step embedding + projection ----------------
__global__ void __launch_bounds__(256) proj_all_kernel(const int* __restrict__ dstep,
                                                       const float* __restrict__ w1a,
                                                       const float* __restrict__ b1a,
                                                       const float* __restrict__ w2a,
                                                       const float* __restrict__ b2a,
                                                       const float* __restrict__ dpwa,
                                                       const float* __restrict__ dpba){
    int i = blockIdx.x;   // layer
    const float* w1 = w1a + i*Cn;
    const float* b1 = b1a + i*Cn;
    const float* w2 = w2a + i*Cn*Cn;
    const float* b2 = b2a + i*Cn;
    const float* dpw = dpwa + i*Cn*Cn;
    const float* dpb = dpba + i*Cn;

    __shared__ float h[Bn][Cn];
    __shared__ float e[Bn][Cn];
    int tid = threadIdx.x;
    int b = tid >> 6, c = tid & 63;

    float d = (float)dstep[b];
    float z = d * w1[c] + b1[c];
    float sg = 1.f / (1.f + expf(-z));
    h[b][c] = z * sg;                     // silu
    __syncthreads();

    float acc = b2[c];
    for (int j = 0; j < Cn; j++) acc += h[b][j] * w2[c*Cn + j];
    e[b][c] = acc;
    __syncthreads();

    float p = dpb[c];
    for (int j = 0; j < Cn; j++) p += e[b][j] * dpw[c*Cn + j];
    g_proj[i*Bn*Cn + b*Cn + c] = p;
}

// ---------------- fused layer: 2-timestep dilated conv + LIF + gate + skip/res 1x1 ----
// 512 threads: cg = tid>>4 (couts {cg, cg+32, cg+64, cg+96}); lg = tid&15 -> 4 l each
// (R7 layout — known good; R8 remap reverted)
__global__ void __launch_bounds__(LTHREADS, 1) layer_kernel(int flip, int layer,
                                                       const float* __restrict__ wconv,
                                                       const float* __restrict__ bconv,
                                                       const float* __restrict__ wskip,
                                                       const float* __restrict__ bskip,
                                                       const float* __restrict__ wres,
                                                       const float* __restrict__ bres,
                                                       int dil){
    const float* x_in  = flip ? g_xB : g_xA;
    float*       x_out = flip ? g_xA : g_xB;

    extern __shared__ float sm[];
    float* wc4  = sm;            // [ci][32 cg][k0:4co, k1:4co, k2:4co]  24576
    float* wskr = wc4  + 24576;  // [ci][32 cg][ws,ws32,wr,wr32]          8192
    float* cb   = wskr + 8192;   // 128
    float* pr   = cb   + 128;    // 64
    float* sbv  = pr   + 64;     // 64
    float* rbv  = sbv  + 64;     // 64
    float* ck   = rbv  + 64;     // [3][128] proj-fold constants          384
    float* tile = ck   + 384;    // 2 timesteps x 3 shifts x [64 ci][64 l] = 24576
                                 // gated overlay (stride 64) reuses s=0 region per timestep
                                 // total = 58048 floats = 232192 B

    const int tid  = threadIdx.x;
    const int b    = blockIdx.y;
    const int l0   = blockIdx.x * TL;
    const int lg   = tid & 15;
    const int cg   = tid >> 4;     // 0..31
    const int jA   = lg * 4;

    // ---- coalesced weight load + scatter repack ----
    for (int i = tid; i < 24576; i += LTHREADS){
        int co = i / 192, r = i % 192, ci = r / 3, k = r % 3;
        int g = co >> 5, cgi = co & 31;
        wc4[((ci*32 + cgi)*3 + k)*4 + g] = wconv[i];
    }
    for (int i = tid; i < 4096; i += LTHREADS){
        int co = i >> 6, ci = i & 63;
        int g = co >> 5, cgi = co & 31;
        wskr[(ci*32 + cgi)*4 + g    ] = wskip[i];
        wskr[(ci*32 + cgi)*4 + g + 2] = wres[i];
    }
    if (tid < 128) cb[tid] = bconv[tid];
    if (tid < 64){
        pr[tid]  = g_proj[layer*Bn*Cn + b*Cn + tid];
        sbv[tid] = bskip[tid];
        rbv[tid] = bres[tid];
    }
    __syncthreads();

    // ---- proj-fold constants: ck[k][cout] = sum_ci wconv[cout,ci,k] * proj[ci] ----
    if (tid < 384){
        int k = tid >> 7;          // 0..2
        int cout = tid & 127;
        int cgi = cout & 31, g = cout >> 5;
        float acc = 0.f;
        for (int ci = 0; ci < Cn; ci++)
            acc += wc4[((ci*32 + cgi)*3 + k)*4 + g] * pr[ci];
        ck[(k << 7) + cout] = acc;
    }
    __syncthreads();

    const float SG1 = 1.f / (1.f + expf(-1.f));
    const float TH1 = tanhf(1.f);

    // folded bias: cb + ck0 + ck1 + ck2
    const unsigned long long cb0 = pk2(cb[cg]    + ck[cg]     + ck[128+cg]     + ck[256+cg]);
    const unsigned long long cb1 = pk2(cb[cg+32] + ck[cg+32]  + ck[128+cg+32]  + ck[256+cg+32]);
    const unsigned long long cb2 = pk2(cb[cg+64] + ck[cg+64]  + ck[128+cg+64]  + ck[256+cg+64]);
    const unsigned long long cb3 = pk2(cb[cg+96] + ck[cg+96]  + ck[128+cg+96]  + ck[256+cg+96]);
    const float sb0 = sbv[cg], sb1 = sbv[cg+32];
    const float rb0 = rbv[cg], rb1 = rbv[cg+32];

    const bool edge = (l0 < dil) || (l0 + TL + dil > Ln);
    float c00=0.f,c01=0.f,c02=0.f,c03=0.f,c20=0.f,c21=0.f,c22=0.f,c23=0.f;
    if (edge){
        c00 = ck[cg];       c01 = ck[cg+32];       c02 = ck[cg+64];       c03 = ck[cg+96];
        c20 = ck[256+cg];   c21 = ck[256+cg+32];   c22 = ck[256+cg+64];   c23 = ck[256+cg+96];
    }

    // LIF membrane: 4 couts x 4 l (persist across tt iterations)
    float vg0[4], vg1[4], vf0[4], vf1[4];
#pragma unroll
    for (int k = 0; k < 4; k++){ vg0[k]=0.f; vg1[k]=0.f; vf0[k]=0.f; vf1[k]=0.f; }

    for (int tt = 0; tt < 2; tt++){
        const int t0 = tt * 2;

        // ---- stage raw x tiles, zero-padded: cp.async path for dil>=4 ----
        if (dil >= 4){
#pragma unroll
            for (int k = 0; k < 2; k++){
                const float* xk = x_in + ((size_t)((t0+k)*Bn + b)) * Cn * Ln;
#pragma unroll
                for (int s = 0; s < 3; s++){
                    int off = l0 + (s - 1) * dil;
#pragma unroll
                    for (int w = 0; w < 2; w++){
                        int q  = tid + w*LTHREADS;   // 0..1023
                        int ci = q >> 4;
                        int jc = (q & 15) << 2;
                        int gl = off + jc;
                        unsigned ss = ((unsigned)gl <= 4092u) ? 16u : 0u;
                        const float* src = ss ? (xk + ci*Ln + gl) : xk;
                        unsigned daddr = (unsigned)__cvta_generic_to_shared(
                                             tile + k*12288 + s*4096 + (ci<<6) + jc);
                        asm volatile("cp.async.ca.shared.global [%0], [%1], 16, %2;"
                                     :: "r"(daddr), "l"(src), "r"(ss) : "memory");
                    }
                }
            }
            asm volatile("cp.async.commit_group;" ::: "memory");
            asm volatile("cp.async.wait_group 0;" ::: "memory");
        } else {
            // scalar path (dil = 1 or 2): raw x, zero-padded
#pragma unroll
            for (int k = 0; k < 2; k++){
                const float* xk = x_in + ((size_t)((t0+k)*Bn + b)) * Cn * Ln;
                float* tk = tile + k*12288;
#pragma unroll 4
                for (int i = tid; i < 3*Cn*TL; i += LTHREADS){
                    int s  = i >> 12;
                    int r  = i & 4095;
                    int ci = r >> 6; int j = r & 63;
                    int gl = l0 + j + (s - 1) * dil;
                    float val = 0.f;
                    if ((unsigned)gl < (unsigned)Ln) val = xk[ci*Ln + gl];
                    tk[i] = val;
                }
            }
        }
        __syncthreads();   // S1: tiles ready

        // ---- dilated conv, 4 couts x 4 l x 2 timesteps per thread ----
        unsigned long long aG0[2][2], aG1[2][2], aF0[2][2], aF1[2][2];
#pragma unroll
        for (int k = 0; k < 2; k++)
#pragma unroll
        for (int q = 0; q < 2; q++){ aG0[k][q]=cb0; aG1[k][q]=cb1; aF0[k][q]=cb2; aF1[k][q]=cb3; }

#pragma unroll 2
        for (int ci = 0; ci < Cn; ci++){
            const float* wrow = wc4 + (ci*32 + cg)*12;
            float4 k0 = *(const float4*)(wrow);
            float4 k1 = *(const float4*)(wrow + 4);
            float4 k2 = *(const float4*)(wrow + 8);
            unsigned long long w00=pk2(k0.x), w01=pk2(k1.x), w02=pk2(k2.x);
            unsigned long long w10=pk2(k0.y), w11=pk2(k1.y), w12=pk2(k2.y);
            unsigned long long w20=pk2(k0.z), w21=pk2(k1.z), w22=pk2(k2.z);
            unsigned long long w30=pk2(k0.w), w31=pk2(k1.w), w32=pk2(k2.w);
#pragma unroll
            for (int k = 0; k < 2; k++){
                const float* trow = tile + k*12288 + (ci << 6);
                ulonglong2 aA = *(const ulonglong2*)(trow + jA);
                ulonglong2 zA = *(const ulonglong2*)(trow + 4096 + jA);
                ulonglong2 pA = *(const ulonglong2*)(trow + 8192 + jA);
                f2fma(aG0[k][0], w00, aA.x); f2fma(aG0[k][1], w00, aA.y);
                f2fma(aG0[k][0], w01, zA.x); f2fma(aG0[k][1], w01, zA.y);
                f2fma(aG0[k][0], w02, pA.x); f2fma(aG0[k][1], w02, pA.y);

                f2fma(aG1[k][0], w10, aA.x); f2fma(aG1[k][1], w10, aA.y);
                f2fma(aG1[k][0], w11, zA.x); f2fma(aG1[k][1], w11, zA.y);
                f2fma(aG1[k][0], w12, pA.x); f2fma(aG1[k][1], w12, pA.y);

                f2fma(aF0[k][0], w20, aA.x); f2fma(aF0[k][1], w20, aA.y);
                f2fma(aF0[k][0], w21, zA.x); f2fma(aF0[k][1], w21, zA.y);
                f2fma(aF0[k][0], w22, pA.x); f2fma(aF0[k][1], w22, pA.y);

                f2fma(aF1[k][0], w30, aA.x); f2fma(aF1[k][1], w30, aA.y);
                f2fma(aF1[k][0], w31, zA.x); f2fma(aF1[k][1], w31, zA.y);
                f2fma(aF1[k][0], w32, pA.x); f2fma(aF1[k][1], w32, pA.y);
            }
        }

        // ---- LIF (hard reset) + gating, both timesteps in order ----
        float gb0[2][4], gb1[2][4];
#pragma unroll
        for (int k = 0; k < 2; k++){
#pragma unroll
            for (int q = 0; q < 2; q++){
#pragma unroll
                for (int h = 0; h < 2; h++){
                    int idx = 2*q + h;
                    float xg0 = h ? hi32(aG0[k][q]) : lo32(aG0[k][q]);
                    float xg1 = h ? hi32(aG1[k][q]) : lo32(aG1[k][q]);
                    float xf0 = h ? hi32(aF0[k][q]) : lo32(aF0[k][q]);
                    float xf1 = h ? hi32(aF1[k][q]) : lo32(aF1[k][q]);

                    if (edge){
                        int gl = l0 + jA + idx;
                        float f0 = (gl < dil) ? 1.f : 0.f;
                        float f2 = (gl >= Ln - dil) ? 1.f : 0.f;
                        xg0 -= f0*c00 + f2*c20;
                        xg1 -= f0*c01 + f2*c21;
                        xf0 -= f0*c02 + f2*c22;
                        xf1 -= f0*c03 + f2*c23;
                    }

                    float s_g0; lif_step(vg0[idx], xg0, s_g0);
                    float s_g1; lif_step(vg1[idx], xg1, s_g1);
                    float s_f0; lif_step(vf0[idx], xf0, s_f0);
                    float s_f1; lif_step(vf1[idx], xf1, s_f1);

                    gb0[k][idx] = ((s_g0 > 0.f) ? SG1 : 0.5f) * ((s_f0 > 0.f) ? TH1 : 0.f);
                    gb1[k][idx] = ((s_g1 > 0.f) ? SG1 : 0.5f) * ((s_f1 > 0.f) ? TH1 : 0.f);
                }
            }
        }
        __syncthreads();   // S2: conv reads of tile done -> safe to overlay gated into s=0 region

#pragma unroll
        for (int k = 0; k < 2; k++){
            float* g0 = tile + k*12288 + (cg << 6);
            float* g1 = tile + k*12288 + ((cg+32) << 6);
            *(float4*)(g0 + jA) = make_float4(gb0[k][0], gb0[k][1], gb0[k][2], gb0[k][3]);
            *(float4*)(g1 + jA) = make_float4(gb1[k][0], gb1[k][1], gb1[k][2], gb1[k][3]);
        }
        __syncthreads();   // S3: gated visible

        // ---- skip / res 1x1 convs for both timesteps (gated in s=0 overlay) ----
        unsigned long long sk0[2][2], sk1[2][2], rs0[2][2], rs1[2][2];
#pragma unroll
        for (int k = 0; k < 2; k++)
#pragma unroll
        for (int q = 0; q < 2; q++){ sk0[k][q]=0ull; sk1[k][q]=0ull; rs0[k][q]=0ull; rs1[k][q]=0ull; }

#pragma unroll 4
        for (int ci = 0; ci < Cn; ci++){
            float4 wv = *(const float4*)(wskr + (ci*32 + cg)*4);
            unsigned long long ws0 = pk2(wv.x), ws1 = pk2(wv.y);
            unsigned long long wr0 = pk2(wv.z), wr1 = pk2(wv.w);
#pragma unroll
            for (int k = 0; k < 2; k++){
                const float* grow = tile + k*12288 + (ci << 6);
                ulonglong2 gA = *(const ulonglong2*)(grow + jA);
                f2fma(sk0[k][0], ws0, gA.x); f2fma(sk0[k][1], ws0, gA.y);
                f2fma(sk1[k][0], ws1, gA.x); f2fma(sk1[k][1], ws1, gA.y);
                f2fma(rs0[k][0], wr0, gA.x); f2fma(rs0[k][1], wr0, gA.y);
                f2fma(rs1[k][0], wr1, gA.x); f2fma(rs1[k][1], wr1, gA.y);
            }
        }

        // ---- global update: skip RMW; x_out = x(center tap smem) + res ----
#pragma unroll
        for (int k = 0; k < 2; k++){
#pragma unroll
            for (int ch = 0; ch < 2; ch++){
                int co = cg + ch*32;
                unsigned long long* skp = ch ? sk1[k] : sk0[k];
                unsigned long long* rsp = ch ? rs1[k] : rs0[k];
                float sbp = ch ? sb1 : sb0;
                float rbp = ch ? rb1 : rb0;
                size_t gbase = ((size_t)((t0+k)*Bn + b)*Cn + co)*Ln + l0;
                float4 sv0 = make_float4(lo32(skp[0])+sbp, hi32(skp[0])+sbp,
                                         lo32(skp[1])+sbp, hi32(skp[1])+sbp);
                float4* skA = (float4*)(g_skip + gbase + jA);
                if (layer != 0){
                    float4 o0 = *skA;
                    sv0.x += o0.x; sv0.y += o0.y; sv0.z += o0.z; sv0.w += o0.w;
                }
                *skA = sv0;

                if (layer != NLAYERS-1){
                    // raw x center tap lives in smem (s=1 region untouched by overlay)
                    float4 a0 = *(const float4*)(tile + k*12288 + 4096 + (co << 6) + jA);
                    a0.x += lo32(rsp[0])+rbp; a0.y += hi32(rsp[0])+rbp;
                    a0.z += lo32(rsp[1])+rbp; a0.w += hi32(rsp[1])+rbp;
                    *(float4*)(x_out + gbase + jA) = a0;
                }
            }
        }
        __syncthreads();   // S4: overlay reads done -> next staging may write tile
    }
}

// ---------------- final: relu(skip) -> 1x1 conv -> LIF -> sum over T ----------------
__global__ void __launch_bounds__(256) out_kernel(const float* __restrict__ wout,
                                                  const float* __restrict__ bout,
                                                  float* __restrict__ out){
    int g = blockIdx.x * 256 + threadIdx.x;     // (b,l)
    int b = g >> 12, l = g & (Ln - 1);
    float bo = bout[0];
    float v = 0.f, ssum = 0.f;
#pragma unroll
    for (int t = 0; t < Tn; t++){
        float acc = bo;
        const float* sk = g_skip + ((size_t)(t*Bn + b))*Cn*Ln + l;
        for (int c = 0; c < Cn; c++){
            float s = sk[(size_t)c*Ln];
            s = (s > 0.f) ? s : 0.f;
            acc += wout[c] * s;
        }
        float sp; lif_step(v, acc, sp);
        ssum += sp;
    }
    out[g] = ssum;
}

// ---------------- launch ----------------
extern "C" void kernel_launch(void* const* d_in, const int* in_sizes, int n_in,
                              void* d_out, int out_size){
    const float* audio   = (const float*)d_in[0];
    const int*   dstep   = (const int*)  d_in[1];
    const float* W_in    = (const float*)d_in[2];
    const float* b_in    = (const float*)d_in[3];
    const float* demb_w1 = (const float*)d_in[4];
    const float* demb_b1 = (const float*)d_in[5];
    const float* demb_w2 = (const float*)d_in[6];
    const float* demb_b2 = (const float*)d_in[7];
    const float* dproj_w = (const float*)d_in[8];
    const float* dproj_b = (const float*)d_in[9];
    const float* conv_w  = (const float*)d_in[10];
    const float* conv_b  = (const float*)d_in[11];
    const float* skip_w  = (const float*)d_in[12];
    const float* skip_b  = (const float*)d_in[13];
    const float* res_w   = (const float*)d_in[14];
    const float* res_b   = (const float*)d_in[15];
    const float* W_out   = (const float*)d_in[16];
    const float* b_out   = (const float*)d_in[17];

    const int SMEM_BYTES = 58048 * 4;   // 232192
    cudaFuncSetAttribute((const void*)layer_kernel,
                         cudaFuncAttributeMaxDynamicSharedMemorySize, SMEM_BYTES);

    enc_kernel<<<(Bn*Ln)/256, 256>>>(audio, W_in, b_in);

    proj_all_kernel<<<NLAYERS, 256>>>(dstep, demb_w1, demb_b1, demb_w2, demb_b2,
                                      dproj_w, dproj_b);

    int flip = 0;
    for (int i = 0; i < NLAYERS; i++){
        layer_kernel<<<dim3(Ln/TL, Bn), LTHREADS, SMEM_BYTES>>>(flip, i,
                                conv_w + i*2*Cn*Cn*3, conv_b + i*2*Cn,
                                skip_w + i*Cn*Cn,     skip_b + i*Cn,
                                res_w  + i*Cn*Cn,     res_b  + i*Cn,
                                1 << i);
        flip ^= 1;
    }

    out_kernel<<<(Bn*Ln)/256, 256>>>(W_out, b_out, (float*)d_out);
}

// round 10
// speedup vs baseline: 1.7446x; 1.0540x over previous
#include <cuda_runtime.h>
#include <math.h>

#define Tn 4
#define Bn 4
#define Cn 64
#define Ln 4096
#define NLAYERS 10
#define TL 64          // l-tile per block
#define LTHREADS 512
#define RCP_TAU (1.0f/1.2f)

// ---------------- scratch (no allocations allowed) ----------------
__device__ float g_xA[Tn*Bn*Cn*Ln];     // 16 MB
__device__ float g_xB[Tn*Bn*Cn*Ln];     // 16 MB
__device__ float g_skip[Tn*Bn*Cn*Ln];   // 16 MB
__device__ float g_proj[NLAYERS*Bn*Cn];

// ---------------- packed f32x2 helpers ----------------
__device__ __forceinline__ unsigned long long pk2(float w){
    unsigned long long r;
    asm("mov.b64 %0, {%1, %1};" : "=l"(r) : "f"(w));
    return r;
}
__device__ __forceinline__ void f2fma(unsigned long long &d, unsigned long long a, unsigned long long b){
    asm("fma.rn.f32x2 %0, %1, %2, %0;" : "+l"(d) : "l"(a), "l"(b));
}
__device__ __forceinline__ float lo32(unsigned long long v){ return __uint_as_float((unsigned)v); }
__device__ __forceinline__ float hi32(unsigned long long v){ return __uint_as_float((unsigned)(v>>32)); }

__device__ __forceinline__ void lif_step(float &v, float x, float &spike){
    v = fmaf(x - v, RCP_TAU, v);
    spike = (v >= 0.5f) ? 1.f : 0.f;
    v *= (1.f - spike);
}

// ---------------- JAX threefry2x32 (key = (0,42)) ----------------
__device__ __forceinline__ unsigned rotl32(unsigned x, int r){ return (x<<r)|(x>>(32-r)); }

__device__ __forceinline__ void threefry_0_42(unsigned x0, unsigned x1, unsigned &o0, unsigned &o1){
    const unsigned ks0 = 0u, ks1 = 42u, ks2 = 0u ^ 42u ^ 0x1BD11BDAu;
    x0 += ks0; x1 += ks1;
#define TF_RND(r) { x0 += x1; x1 = rotl32(x1,(r)); x1 ^= x0; }
    TF_RND(13) TF_RND(15) TF_RND(26) TF_RND(6)
    x0 += ks1; x1 += ks2 + 1u;
    TF_RND(17) TF_RND(29) TF_RND(16) TF_RND(24)
    x0 += ks2; x1 += ks0 + 2u;
    TF_RND(13) TF_RND(15) TF_RND(26) TF_RND(6)
    x0 += ks0; x1 += ks1 + 3u;
    TF_RND(17) TF_RND(29) TF_RND(16) TF_RND(24)
    x0 += ks1; x1 += ks2 + 4u;
    TF_RND(13) TF_RND(15) TF_RND(26) TF_RND(6)
    x0 += ks2; x1 += ks0 + 5u;
#undef TF_RND
    o0 = x0; o1 = x1;
}
__device__ __forceinline__ float bits2unit(unsigned b){
    return __uint_as_float((b >> 9) | 0x3f800000u) - 1.0f;
}

// ---------------- encoder: poisson + input conv(1x1) + LIF ----------------
__global__ void __launch_bounds__(256) enc_kernel(const float* __restrict__ audio,
                                                  const float* __restrict__ w_in,
                                                  const float* __restrict__ b_in){
    int g = blockIdx.x * 256 + threadIdx.x;      // 0..16383  (b,l)
    int b = g >> 12, l = g & (Ln - 1);
    float a = audio[g];

    unsigned n0 = (unsigned)(b * Ln + l);
    unsigned o0, o1, o2, o3;
    threefry_0_42(n0,           n0 + 32768u, o0, o2);
    threefry_0_42(n0 + 16384u,  n0 + 49152u, o1, o3);

    float sp[4];
    sp[0] = (bits2unit(o0) < a) ? 1.f : 0.f;
    sp[1] = (bits2unit(o1) < a) ? 1.f : 0.f;
    sp[2] = (bits2unit(o2) < a) ? 1.f : 0.f;
    sp[3] = (bits2unit(o3) < a) ? 1.f : 0.f;

    for (int c = 0; c < Cn; c++){
        float w = w_in[c], bi = b_in[c];
        float v = 0.f;
#pragma unroll
        for (int t = 0; t < Tn; t++){
            float x = w * sp[t] + bi;
            float s; lif_step(v, x, s);
            int idx = ((t*Bn + b)*Cn + c)*Ln + l;
            g_xA[idx] = s;
        }
    }
}

// ---------------- ALL layers' diffusion-step embedding + projection ----------------
__global__ void __launch_bounds__(256) proj_all_kernel(const int* __restrict__ dstep,
                                                       const float* __restrict__ w1a,
                                                       const float* __restrict__ b1a,
                                                       const float* __restrict__ w2a,
                                                       const float* __restrict__ b2a,
                                                       const float* __restrict__ dpwa,
                                                       const float* __restrict__ dpba){
    int i = blockIdx.x;
    const float* w1 = w1a + i*Cn;
    const float* b1 = b1a + i*Cn;
    const float* w2 = w2a + i*Cn*Cn;
    const float* b2 = b2a + i*Cn;
    const float* dpw = dpwa + i*Cn*Cn;
    const float* dpb = dpba + i*Cn;

    __shared__ float h[Bn][Cn];
    __shared__ float e[Bn][Cn];
    int tid = threadIdx.x;
    int b = tid >> 6, c = tid & 63;

    float d = (float)dstep[b];
    float z = d * w1[c] + b1[c];
    float sg = 1.f / (1.f + expf(-z));
    h[b][c] = z * sg;
    __syncthreads();

    float acc = b2[c];
    for (int j = 0; j < Cn; j++) acc += h[b][j] * w2[c*Cn + j];
    e[b][c] = acc;
    __syncthreads();

    float p = dpb[c];
    for (int j = 0; j < Cn; j++) p += e[b][j] * dpw[c*Cn + j];
    g_proj[i*Bn*Cn + b*Cn + c] = p;
}

// ---------------- fused layer: timestep-split conv (nc=8) + LIF exchange ----------
// 512 threads: lg = tid&15 (4 l at jA=lg*4); jg = (tid>>4)&15 -> couts {jg+16m, m=0..7};
// ht = tid>>8 -> timestep within pass. ht=1 publishes conv accs via smem; ht=0 owns LIF.
__global__ void __launch_bounds__(LTHREADS, 1) layer_kernel(int flip, int layer,
                                                       const float* __restrict__ wconv,
                                                       const float* __restrict__ bconv,
                                                       const float* __restrict__ wskip,
                                                       const float* __restrict__ bskip,
                                                       const float* __restrict__ wres,
                                                       const float* __restrict__ bres,
                                                       int dil){
    const float* x_in  = flip ? g_xB : g_xA;
    float*       x_out = flip ? g_xA : g_xB;

    extern __shared__ float sm[];
    float* wc8  = sm;            // [ci][16 jg][3 tap][8 m]               24576
    float* wskr = wc8  + 24576;  // [ci][16 jg][s0..s3, r0..r3]            8192
    float* cb   = wskr + 8192;   // raw conv bias -> rearranged folded bias 128
    float* pr   = cb   + 128;    // 64
    float* sbv  = pr   + 64;     // 64
    float* rbv  = sbv  + 64;     // 64
    float* ck   = rbv  + 64;     // [3][128] proj-fold constants           384
    float* tile = ck   + 384;    // 2 k x 3 shifts x [64 ci][64 l] = 24576
                                 // post-conv overlays: gated t -> tile[k= t][s0];
                                 // acc exchange -> s2 regions of both k
                                 // total = 58048 floats = 232192 B

    const int tid  = threadIdx.x;
    const int b    = blockIdx.y;
    const int l0   = blockIdx.x * TL;
    const int lg   = tid & 15;
    const int jg   = (tid >> 4) & 15;
    const int ht   = tid >> 8;          // 0 or 1
    const int jA   = lg * 4;
    const int thr  = tid & 255;

    // ---- coalesced weight load + scatter repack ----
    for (int i = tid; i < 24576; i += LTHREADS){
        int co = i / 192, r = i % 192, ci = r / 3, k = r % 3;
        int jgc = co & 15, mc = co >> 4;
        wc8[((ci*16 + jgc)*3 + k)*8 + mc] = wconv[i];
    }
    for (int i = tid; i < 4096; i += LTHREADS){
        int co = i >> 6, ci = i & 63;
        int jgc = co & 15, mc = co >> 4;     // mc 0..3
        wskr[(ci*16 + jgc)*8 + mc    ] = wskip[i];
        wskr[(ci*16 + jgc)*8 + 4 + mc] = wres[i];
    }
    if (tid < 128) cb[tid] = bconv[tid];
    if (tid < 64){
        pr[tid]  = g_proj[layer*Bn*Cn + b*Cn + tid];
        sbv[tid] = bskip[tid];
        rbv[tid] = bres[tid];
    }
    __syncthreads();

    // ---- proj-fold constants: ck[k][cout] = sum_ci w[cout,ci,k] * proj[ci] ----
    if (tid < 384){
        int k = tid >> 7;
        int cout = tid & 127;
        int jgc = cout & 15, mc = cout >> 4;
        float acc = 0.f;
        for (int ci = 0; ci < Cn; ci++)
            acc += wc8[((ci*16 + jgc)*3 + k)*8 + mc] * pr[ci];
        ck[(k << 7) + cout] = acc;
    }
    __syncthreads();

    // ---- folded bias, rearranged in place into cb[(jg<<3)+m] ----
    float fbv = 0.f;
    if (tid < 128){
        int c = tid;
        fbv = cb[c] + ck[c] + ck[128+c] + ck[256+c];
    }
    __syncthreads();
    if (tid < 128){
        int c = tid;
        cb[((c & 15) << 3) + (c >> 4)] = fbv;
    }
    __syncthreads();

    const float SG1 = 1.f / (1.f + expf(-1.f));
    const float TH1 = tanhf(1.f);
    const bool edge = (l0 < dil) || (l0 + TL + dil > Ln);

    // LIF state (only meaningful in ht==0 threads): gate/filt v for 4 ch x 4 l
    float vG[16], vF[16];
#pragma unroll
    for (int k = 0; k < 16; k++){ vG[k]=0.f; vF[k]=0.f; }

    for (int tt = 0; tt < 2; tt++){
        const int t0 = tt * 2;

        // ---- stage raw x tiles, zero-padded ----
        if (dil >= 4){
#pragma unroll
            for (int k = 0; k < 2; k++){
                const float* xk = x_in + ((size_t)((t0+k)*Bn + b)) * Cn * Ln;
#pragma unroll
                for (int s = 0; s < 3; s++){
                    int off = l0 + (s - 1) * dil;
#pragma unroll
                    for (int w = 0; w < 2; w++){
                        int q  = tid + w*LTHREADS;   // 0..1023
                        int ci = q >> 4;
                        int jc = (q & 15) << 2;
                        int gl = off + jc;
                        unsigned ss = ((unsigned)gl <= 4092u) ? 16u : 0u;
                        const float* src = ss ? (xk + ci*Ln + gl) : xk;
                        unsigned daddr = (unsigned)__cvta_generic_to_shared(
                                             tile + k*12288 + s*4096 + (ci<<6) + jc);
                        asm volatile("cp.async.ca.shared.global [%0], [%1], 16, %2;"
                                     :: "r"(daddr), "l"(src), "r"(ss) : "memory");
                    }
                }
            }
            asm volatile("cp.async.commit_group;" ::: "memory");
            asm volatile("cp.async.wait_group 0;" ::: "memory");
        } else {
#pragma unroll
            for (int k = 0; k < 2; k++){
                const float* xk = x_in + ((size_t)((t0+k)*Bn + b)) * Cn * Ln;
                float* tk = tile + k*12288;
#pragma unroll 4
                for (int i = tid; i < 3*Cn*TL; i += LTHREADS){
                    int s  = i >> 12;
                    int r  = i & 4095;
                    int ci = r >> 6; int j = r & 63;
                    int gl = l0 + j + (s - 1) * dil;
                    float val = 0.f;
                    if ((unsigned)gl < (unsigned)Ln) val = xk[ci*Ln + gl];
                    tk[i] = val;
                }
            }
        }
        __syncthreads();   // S1: tiles ready

        // ---- conv: 8 couts x 4 l x own timestep (ht) ----
        // accP[p][l]: u64 = couts (2p, 2p+1) of Cset at l
        unsigned long long accP[4][4];
        {
            ulonglong2 fbA = *(const ulonglong2*)(cb + (jg << 3));
            ulonglong2 fbB = *(const ulonglong2*)(cb + (jg << 3) + 4);
#pragma unroll
            for (int l = 0; l < 4; l++){
                accP[0][l] = fbA.x; accP[1][l] = fbA.y;
                accP[2][l] = fbB.x; accP[3][l] = fbB.y;
            }
        }
        const float* tbase = tile + ht*12288;
#pragma unroll 2
        for (int ci = 0; ci < Cn; ci++){
            const float* trow = tbase + (ci << 6);
            ulonglong2 xa = *(const ulonglong2*)(trow + jA);
            ulonglong2 xz = *(const ulonglong2*)(trow + 4096 + jA);
            ulonglong2 xp = *(const ulonglong2*)(trow + 8192 + jA);
            const float* wrow = wc8 + (ci*16 + jg)*24;
#pragma unroll
            for (int tap = 0; tap < 3; tap++){
                ulonglong2 wA = *(const ulonglong2*)(wrow + tap*8);
                ulonglong2 wB = *(const ulonglong2*)(wrow + tap*8 + 4);
                ulonglong2 xs_ = (tap == 0) ? xa : (tap == 1) ? xz : xp;
                unsigned long long xd0 = pk2(lo32(xs_.x));
                unsigned long long xd1 = pk2(hi32(xs_.x));
                unsigned long long xd2 = pk2(lo32(xs_.y));
                unsigned long long xd3 = pk2(hi32(xs_.y));
                f2fma(accP[0][0], wA.x, xd0); f2fma(accP[0][1], wA.x, xd1);
                f2fma(accP[0][2], wA.x, xd2); f2fma(accP[0][3], wA.x, xd3);
                f2fma(accP[1][0], wA.y, xd0); f2fma(accP[1][1], wA.y, xd1);
                f2fma(accP[1][2], wA.y, xd2); f2fma(accP[1][3], wA.y, xd3);
                f2fma(accP[2][0], wB.x, xd0); f2fma(accP[2][1], wB.x, xd1);
                f2fma(accP[2][2], wB.x, xd2); f2fma(accP[2][3], wB.x, xd3);
                f2fma(accP[3][0], wB.y, xd0); f2fma(accP[3][1], wB.y, xd1);
                f2fma(accP[3][2], wB.y, xd2); f2fma(accP[3][3], wB.y, xd3);
            }
        }
        __syncthreads();   // S2: all conv tile reads done (incl s2)

        // ---- exchange: ht=1 publishes t1 accs into s2 regions ----
        unsigned long long* xs0 = (unsigned long long*)(tile + 8192);          // k0 s2
        unsigned long long* xs1 = (unsigned long long*)(tile + 12288 + 8192);  // k1 s2
        if (ht == 1){
#pragma unroll
            for (int p = 0; p < 2; p++)
#pragma unroll
            for (int l = 0; l < 4; l++)
                xs0[(p*4 + l)*256 + thr] = accP[p][l];
#pragma unroll
            for (int p = 2; p < 4; p++)
#pragma unroll
            for (int l = 0; l < 4; l++)
                xs1[((p-2)*4 + l)*256 + thr] = accP[p][l];
        }
        __syncthreads();   // S2b: exchange visible

        // ---- LIF (both t) + gating, consumer = ht==0 threads ----
        if (ht == 0){
#pragma unroll
            for (int p = 0; p < 2; p++){
                float g0t0[4], g1t0[4], g0t1[4], g1t1[4];
#pragma unroll
                for (int l = 0; l < 4; l++){
                    float a0g0 = lo32(accP[p][l]),   a0g1 = hi32(accP[p][l]);
                    float a0f0 = lo32(accP[p+2][l]), a0f1 = hi32(accP[p+2][l]);
                    unsigned long long t1g = xs0[(p*4 + l)*256 + thr];
                    unsigned long long t1f = xs1[(p*4 + l)*256 + thr];
                    float a1g0 = lo32(t1g), a1g1 = hi32(t1g);
                    float a1f0 = lo32(t1f), a1f1 = hi32(t1f);

                    if (edge){
                        int gl = l0 + jA + l;
                        float f0 = (gl < dil) ? 1.f : 0.f;
                        float f2 = (gl >= Ln - dil) ? 1.f : 0.f;
                        int cg0 = jg + 32*p;
                        float e_g0 = f0*ck[cg0]      + f2*ck[256+cg0];
                        float e_g1 = f0*ck[cg0+16]   + f2*ck[256+cg0+16];
                        float e_f0 = f0*ck[cg0+64]   + f2*ck[256+cg0+64];
                        float e_f1 = f0*ck[cg0+80]   + f2*ck[256+cg0+80];
                        a0g0 -= e_g0; a1g0 -= e_g0;
                        a0g1 -= e_g1; a1g1 -= e_g1;
                        a0f0 -= e_f0; a1f0 -= e_f0;
                        a0f1 -= e_f1; a1f1 -= e_f1;
                    }

                    int i0 = (2*p)*4 + l, i1 = (2*p+1)*4 + l;
                    float sg, sf;
                    // t0
                    lif_step(vG[i0], a0g0, sg); lif_step(vF[i0], a0f0, sf);
                    g0t0[l] = ((sg > 0.f) ? SG1 : 0.5f) * ((sf > 0.f) ? TH1 : 0.f);
                    lif_step(vG[i1], a0g1, sg); lif_step(vF[i1], a0f1, sf);
                    g1t0[l] = ((sg > 0.f) ? SG1 : 0.5f) * ((sf > 0.f) ? TH1 : 0.f);
                    // t1
                    lif_step(vG[i0], a1g0, sg); lif_step(vF[i0], a1f0, sf);
                    g0t1[l] = ((sg > 0.f) ? SG1 : 0.5f) * ((sf > 0.f) ? TH1 : 0.f);
                    lif_step(vG[i1], a1g1, sg); lif_step(vF[i1], a1f1, sf);
                    g1t1[l] = ((sg > 0.f) ? SG1 : 0.5f) * ((sf > 0.f) ? TH1 : 0.f);
                }
                int ch0 = jg + 32*p;          // gated ch for m=2p
                int ch1 = ch0 + 16;           // m=2p+1
                *(float4*)(tile +           (ch0 << 6) + jA) = make_float4(g0t0[0], g0t0[1], g0t0[2], g0t0[3]);
                *(float4*)(tile +           (ch1 << 6) + jA) = make_float4(g1t0[0], g1t0[1], g1t0[2], g1t0[3]);
                *(float4*)(tile + 12288 +   (ch0 << 6) + jA) = make_float4(g0t1[0], g0t1[1], g0t1[2], g0t1[3]);
                *(float4*)(tile + 12288 +   (ch1 << 6) + jA) = make_float4(g1t1[0], g1t1[1], g1t1[2], g1t1[3]);
            }
        }
        __syncthreads();   // S3: gated overlays visible

        // ---- skip / res 1x1 for own timestep ----
        unsigned long long sk[2][4], rs[2][4];   // [ch-pair (m0m1 / m2m3)][l]
#pragma unroll
        for (int p = 0; p < 2; p++)
#pragma unroll
        for (int l = 0; l < 4; l++){ sk[p][l] = 0ull; rs[p][l] = 0ull; }

        const float* gbasep = tile + ht*12288;
#pragma unroll 4
        for (int ci = 0; ci < Cn; ci++){
            ulonglong2 g = *(const ulonglong2*)(gbasep + (ci << 6) + jA);
            unsigned long long gd0 = pk2(lo32(g.x));
            unsigned long long gd1 = pk2(hi32(g.x));
            unsigned long long gd2 = pk2(lo32(g.y));
            unsigned long long gd3 = pk2(hi32(g.y));
            const float* wb = wskr + (ci*16 + jg)*8;
            ulonglong2 wsv = *(const ulonglong2*)(wb);
            ulonglong2 wrv = *(const ulonglong2*)(wb + 4);
            f2fma(sk[0][0], wsv.x, gd0); f2fma(sk[0][1], wsv.x, gd1);
            f2fma(sk[0][2], wsv.x, gd2); f2fma(sk[0][3], wsv.x, gd3);
            f2fma(sk[1][0], wsv.y, gd0); f2fma(sk[1][1], wsv.y, gd1);
            f2fma(sk[1][2], wsv.y, gd2); f2fma(sk[1][3], wsv.y, gd3);
            f2fma(rs[0][0], wrv.x, gd0); f2fma(rs[0][1], wrv.x, gd1);
            f2fma(rs[0][2], wrv.x, gd2); f2fma(rs[0][3], wrv.x, gd3);
            f2fma(rs[1][0], wrv.y, gd0); f2fma(rs[1][1], wrv.y, gd1);
            f2fma(rs[1][2], wrv.y, gd2); f2fma(rs[1][3], wrv.y, gd3);
        }

        // ---- global update for own timestep: 4 ch ----
        {
            int t = t0 + ht;
#pragma unroll
            for (int m = 0; m < 4; m++){
                int ch = jg + 16*m;
                int p = m >> 1;
                bool hi = (m & 1);
                float s0 = hi ? hi32(sk[p][0]) : lo32(sk[p][0]);
                float s1 = hi ? hi32(sk[p][1]) : lo32(sk[p][1]);
                float s2 = hi ? hi32(sk[p][2]) : lo32(sk[p][2]);
                float s3 = hi ? hi32(sk[p][3]) : lo32(sk[p][3]);
                float r0 = hi ? hi32(rs[p][0]) : lo32(rs[p][0]);
                float r1 = hi ? hi32(rs[p][1]) : lo32(rs[p][1]);
                float r2 = hi ? hi32(rs[p][2]) : lo32(rs[p][2]);
                float r3 = hi ? hi32(rs[p][3]) : lo32(rs[p][3]);
                float sbp = sbv[ch], rbp = rbv[ch];
                size_t gbase = ((size_t)(t*Bn + b)*Cn + ch)*Ln + l0;

                float4 sv = make_float4(s0+sbp, s1+sbp, s2+sbp, s3+sbp);
                float4* skA = (float4*)(g_skip + gbase + jA);
                if (layer != 0){
                    float4 o0 = *skA;
                    sv.x += o0.x; sv.y += o0.y; sv.z += o0.z; sv.w += o0.w;
                }
                *skA = sv;

                if (layer != NLAYERS-1){
                    float4 a0 = *(const float4*)(tile + ht*12288 + 4096 + (ch << 6) + jA);
                    a0.x += r0+rbp; a0.y += r1+rbp; a0.z += r2+rbp; a0.w += r3+rbp;
                    *(float4*)(x_out + gbase + jA) = a0;
                }
            }
        }
        __syncthreads();   // S4: overlay/center reads done -> next staging may write tile
    }
}

// ---------------- final: relu(skip) -> 1x1 conv -> LIF -> sum over T ----------------
__global__ void __launch_bounds__(256) out_kernel(const float* __restrict__ wout,
                                                  const float* __restrict__ bout,
                                                  float* __restrict__ out){
    int g = blockIdx.x * 256 + threadIdx.x;
    int b = g >> 12, l = g & (Ln - 1);
    float bo = bout[0];
    float v = 0.f, ssum = 0.f;
#pragma unroll
    for (int t = 0; t < Tn; t++){
        float acc = bo;
        const float* sk = g_skip + ((size_t)(t*Bn + b))*Cn*Ln + l;
        for (int c = 0; c < Cn; c++){
            float s = sk[(size_t)c*Ln];
            s = (s > 0.f) ? s : 0.f;
            acc += wout[c] * s;
        }
        float sp; lif_step(v, acc, sp);
        ssum += sp;
    }
    out[g] = ssum;
}

// ---------------- launch ----------------
extern "C" void kernel_launch(void* const* d_in, const int* in_sizes, int n_in,
                              void* d_out, int out_size){
    const float* audio   = (const float*)d_in[0];
    const int*   dstep   = (const int*)  d_in[1];
    const float* W_in    = (const float*)d_in[2];
    const float* b_in    = (const float*)d_in[3];
    const float* demb_w1 = (const float*)d_in[4];
    const float* demb_b1 = (const float*)d_in[5];
    const float* demb_w2 = (const float*)d_in[6];
    const float* demb_b2 = (const float*)d_in[7];
    const float* dproj_w = (const float*)d_in[8];
    const float* dproj_b = (const float*)d_in[9];
    const float* conv_w  = (const float*)d_in[10];
    const float* conv_b  = (const float*)d_in[11];
    const float* skip_w  = (const float*)d_in[12];
    const float* skip_b  = (const float*)d_in[13];
    const float* res_w   = (const float*)d_in[14];
    const float* res_b   = (const float*)d_in[15];
    const float* W_out   = (const float*)d_in[16];
    const float* b_out   = (const float*)d_in[17];

    const int SMEM_BYTES = 58048 * 4;   // 232192
    cudaFuncSetAttribute((const void*)layer_kernel,
                         cudaFuncAttributeMaxDynamicSharedMemorySize, SMEM_BYTES);

    enc_kernel<<<(Bn*Ln)/256, 256>>>(audio, W_in, b_in);

    proj_all_kernel<<<NLAYERS, 256>>>(dstep, demb_w1, demb_b1, demb_w2, demb_b2,
                                      dproj_w, dproj_b);

    int flip = 0;
    for (int i = 0; i < NLAYERS; i++){
        layer_kernel<<<dim3(Ln/TL, Bn), LTHREADS, SMEM_BYTES>>>(flip, i,
                                conv_w + i*2*Cn*Cn*3, conv_b + i*2*Cn,
                                skip_w + i*Cn*Cn,     skip_b + i*Cn,
                                res_w  + i*Cn*Cn,     res_b  + i*Cn,
                                1 << i);
        flip ^= 1;
    }

    out_kernel<<<(Bn*Ln)/256, 256>>>(W_out, b_out, (float*)d_out);
}